// round 1
// baseline (speedup 1.0000x reference)
#include <cuda_runtime.h>

// Problem constants (fixed by reference setup_inputs)
#define HIDDEN 512
#define HEADS  8
#define HD     64
#define BATCH  2
#define SEQ    4096
#define BH     (BATCH * HEADS)      // 16
#define MTOT   (BATCH * SEQ)        // 8192

// Scratch (allocation-free rule: __device__ globals)
__device__ float g_q[(size_t)BH * SEQ * HD];
__device__ float g_k[(size_t)BH * SEQ * HD];
__device__ float g_v[(size_t)BH * SEQ * HD];
__device__ float g_attn[(size_t)MTOT * HIDDEN];

// ---------------------------------------------------------------------------
// Tiled fp32 GEMM: out[M=8192, N=512] = X[8192,512] @ W[512,512] + bias
// BM=128, BN=64, BK=16; 256 threads as 16x16, each computes 8x4.
// HEADSPLIT=1: write into [B*H, S, 64] layout (BN=64 == one head, h=blockIdx.x)
// ---------------------------------------------------------------------------
template <int HEADSPLIT>
__global__ __launch_bounds__(256) void gemm512_kernel(
    const float* __restrict__ X, const float* __restrict__ W,
    const float* __restrict__ bias, float* __restrict__ out)
{
    __shared__ float Xt[16 * 129];   // transposed X tile [k][m], stride 129
    __shared__ float Ws[16 * 64];    // W tile [k][n]

    const int tx = threadIdx.x & 15;
    const int ty = threadIdx.x >> 4;
    const int n0 = blockIdx.x * 64;
    const int m0 = blockIdx.y * 128;

    float acc[8][4];
#pragma unroll
    for (int i = 0; i < 8; ++i)
#pragma unroll
        for (int j = 0; j < 4; ++j) acc[i][j] = 0.f;

    for (int kt = 0; kt < HIDDEN; kt += 16) {
        __syncthreads();
        // Load X tile [128 x 16], store transposed into Xt
        for (int i = threadIdx.x; i < 512; i += 256) {
            int m  = i >> 2;
            int k4 = (i & 3) * 4;
            float4 v = *(const float4*)(X + (size_t)(m0 + m) * HIDDEN + kt + k4);
            Xt[(k4 + 0) * 129 + m] = v.x;
            Xt[(k4 + 1) * 129 + m] = v.y;
            Xt[(k4 + 2) * 129 + m] = v.z;
            Xt[(k4 + 3) * 129 + m] = v.w;
        }
        // Load W tile [16 x 64], natural layout (exactly 1 float4/thread)
        {
            int i  = threadIdx.x;
            int k  = i >> 4;
            int n4 = (i & 15) * 4;
            *(float4*)(Ws + k * 64 + n4) =
                *(const float4*)(W + (size_t)(kt + k) * HIDDEN + n0 + n4);
        }
        __syncthreads();

#pragma unroll
        for (int kk = 0; kk < 16; ++kk) {
            float a[8];
#pragma unroll
            for (int i = 0; i < 8; ++i) a[i] = Xt[kk * 129 + ty * 8 + i];
            float4 b = *(const float4*)(Ws + kk * 64 + tx * 4);
#pragma unroll
            for (int i = 0; i < 8; ++i) {
                acc[i][0] += a[i] * b.x;
                acc[i][1] += a[i] * b.y;
                acc[i][2] += a[i] * b.z;
                acc[i][3] += a[i] * b.w;
            }
        }
    }

    float4 bv = *(const float4*)(bias + n0 + tx * 4);
#pragma unroll
    for (int i = 0; i < 8; ++i) {
        int m = m0 + ty * 8 + i;
        float4 r = make_float4(acc[i][0] + bv.x, acc[i][1] + bv.y,
                               acc[i][2] + bv.z, acc[i][3] + bv.w);
        if (HEADSPLIT) {
            int b_ = m >> 12;          // m / SEQ
            int s_ = m & (SEQ - 1);    // m % SEQ
            int h  = blockIdx.x;       // n0 / 64
            *(float4*)(out + ((size_t)(b_ * HEADS + h) * SEQ + s_) * HD + tx * 4) = r;
        } else {
            *(float4*)(out + (size_t)m * HIDDEN + n0 + tx * 4) = r;
        }
    }
}

// ---------------------------------------------------------------------------
// Flash attention, fp32. Per CTA: 128 q-rows of one (b,h); loop 64-key tiles.
// 256 threads as 16x16; each owns 8 q-rows x 4 cols.
// smem: Qs[128][64] (pre-scaled), Kt[64][64] (transposed), Vs[64][64], Ps[128][68]
// ---------------------------------------------------------------------------
#define ATTN_SMEM_FLOATS (128 * 64 + 64 * 64 + 64 * 64 + 128 * 68)
#define ATTN_SMEM_BYTES  (ATTN_SMEM_FLOATS * 4)

__global__ __launch_bounds__(256, 2) void attn_kernel(
    const float* __restrict__ Qg, const float* __restrict__ Kg,
    const float* __restrict__ Vg, float* __restrict__ Og)
{
    extern __shared__ float sm[];
    float* Qs = sm;                 // 8192 floats
    float* Kt = sm + 8192;          // 4096 floats, [k][key]
    float* Vs = sm + 12288;         // 4096 floats, [key][hd]
    float* Ps = sm + 16384;         // 128*68 floats

    const int tid = threadIdx.x;
    const int tx  = tid & 15;
    const int ty  = tid >> 4;
    const int bh  = blockIdx.y;             // 0..15
    const int q0  = blockIdx.x * 128;

    const float* Qp = Qg + ((size_t)bh * SEQ + q0) * HD;
    const float* Kp = Kg + (size_t)bh * SEQ * HD;
    const float* Vp = Vg + (size_t)bh * SEQ * HD;

    // Load Q tile (contiguous), fold in softmax scale 1/sqrt(64)
    for (int i = tid; i < 2048; i += 256) {
        float4 v = ((const float4*)Qp)[i];
        v.x *= 0.125f; v.y *= 0.125f; v.z *= 0.125f; v.w *= 0.125f;
        ((float4*)Qs)[i] = v;
    }

    float O_[8][4];
    float m_[8], l_[8];
#pragma unroll
    for (int i = 0; i < 8; ++i) {
        m_[i] = -1e30f; l_[i] = 0.f;
#pragma unroll
        for (int j = 0; j < 4; ++j) O_[i][j] = 0.f;
    }

    for (int t = 0; t < SEQ / 64; ++t) {
        __syncthreads();   // previous iter done reading Kt/Vs (and Qs ready on t==0)
        const float* Kpt = Kp + (size_t)t * 64 * HD;
        const float* Vpt = Vp + (size_t)t * 64 * HD;
        // V tile: contiguous copy
        for (int i = tid; i < 1024; i += 256)
            ((float4*)Vs)[i] = ((const float4*)Vpt)[i];
        // K tile: transpose into Kt[k][key] (conflict-free smem writes)
        for (int i = tid; i < 1024; i += 256) {
            int n  = i & 63;
            int k4 = (i >> 6) * 4;
            float4 v = *(const float4*)(Kpt + n * HD + k4);
            Kt[(k4 + 0) * 64 + n] = v.x;
            Kt[(k4 + 1) * 64 + n] = v.y;
            Kt[(k4 + 2) * 64 + n] = v.z;
            Kt[(k4 + 3) * 64 + n] = v.w;
        }
        __syncthreads();

        // S = Q @ K^T (scaled) for this 128x64 tile
        float s_[8][4];
#pragma unroll
        for (int i = 0; i < 8; ++i)
#pragma unroll
            for (int j = 0; j < 4; ++j) s_[i][j] = 0.f;

#pragma unroll 8
        for (int kk = 0; kk < 64; ++kk) {
            float a[8];
#pragma unroll
            for (int i = 0; i < 8; ++i) a[i] = Qs[(ty * 8 + i) * 64 + kk];
            float4 b = *(const float4*)(Kt + kk * 64 + tx * 4);
#pragma unroll
            for (int i = 0; i < 8; ++i) {
                s_[i][0] += a[i] * b.x;
                s_[i][1] += a[i] * b.y;
                s_[i][2] += a[i] * b.z;
                s_[i][3] += a[i] * b.w;
            }
        }

        // Online softmax (row stats reduced across the 16-lane tx group)
#pragma unroll
        for (int i = 0; i < 8; ++i) {
            float mx = fmaxf(fmaxf(s_[i][0], s_[i][1]), fmaxf(s_[i][2], s_[i][3]));
#pragma unroll
            for (int off = 8; off; off >>= 1)
                mx = fmaxf(mx, __shfl_xor_sync(0xffffffffu, mx, off));
            float mnew = fmaxf(m_[i], mx);
            float corr = __expf(m_[i] - mnew);
            m_[i] = mnew;
            float p0 = __expf(s_[i][0] - mnew);
            float p1 = __expf(s_[i][1] - mnew);
            float p2 = __expf(s_[i][2] - mnew);
            float p3 = __expf(s_[i][3] - mnew);
            float rs = (p0 + p1) + (p2 + p3);
#pragma unroll
            for (int off = 8; off; off >>= 1)
                rs += __shfl_xor_sync(0xffffffffu, rs, off);
            l_[i] = l_[i] * corr + rs;
#pragma unroll
            for (int j = 0; j < 4; ++j) O_[i][j] *= corr;
            *(float4*)(Ps + (ty * 8 + i) * 68 + tx * 4) = make_float4(p0, p1, p2, p3);
        }
        __syncthreads();   // Ps visible to all; Kt free

        // O += P @ V
#pragma unroll 8
        for (int kk = 0; kk < 64; ++kk) {
            float a[8];
#pragma unroll
            for (int i = 0; i < 8; ++i) a[i] = Ps[(ty * 8 + i) * 68 + kk];
            float4 b = *(const float4*)(Vs + kk * 64 + tx * 4);
#pragma unroll
            for (int i = 0; i < 8; ++i) {
                O_[i][0] += a[i] * b.x;
                O_[i][1] += a[i] * b.y;
                O_[i][2] += a[i] * b.z;
                O_[i][3] += a[i] * b.w;
            }
        }
    }

    // Epilogue: O /= l, write to g_attn in flat [B*S, 512] layout
    const int b_ = bh >> 3;
    const int h  = bh & 7;
#pragma unroll
    for (int i = 0; i < 8; ++i) {
        float inv = 1.0f / l_[i];
        float4 r = make_float4(O_[i][0] * inv, O_[i][1] * inv,
                               O_[i][2] * inv, O_[i][3] * inv);
        size_t row = (size_t)b_ * SEQ + q0 + ty * 8 + i;
        *(float4*)(Og + row * HIDDEN + h * HD + tx * 4) = r;
    }
}

// ---------------------------------------------------------------------------
extern "C" void kernel_launch(void* const* d_in, const int* in_sizes, int n_in,
                              void* d_out, int out_size)
{
    const float* x  = (const float*)d_in[0];
    const float* Wq = (const float*)d_in[1];
    const float* bq = (const float*)d_in[2];
    const float* Wk = (const float*)d_in[3];
    const float* bk = (const float*)d_in[4];
    const float* Wv = (const float*)d_in[5];
    const float* bv = (const float*)d_in[6];
    const float* Wo = (const float*)d_in[7];
    const float* bo = (const float*)d_in[8];
    float* out = (float*)d_out;

    float *gq, *gk, *gv, *ga;
    cudaGetSymbolAddress((void**)&gq, g_q);
    cudaGetSymbolAddress((void**)&gk, g_k);
    cudaGetSymbolAddress((void**)&gv, g_v);
    cudaGetSymbolAddress((void**)&ga, g_attn);

    cudaFuncSetAttribute(attn_kernel,
                         cudaFuncAttributeMaxDynamicSharedMemorySize,
                         ATTN_SMEM_BYTES);

    dim3 gg(HIDDEN / 64, MTOT / 128);   // (8, 64)
    gemm512_kernel<1><<<gg, 256>>>(x, Wq, bq, gq);
    gemm512_kernel<1><<<gg, 256>>>(x, Wk, bk, gk);
    gemm512_kernel<1><<<gg, 256>>>(x, Wv, bv, gv);

    attn_kernel<<<dim3(SEQ / 128, BH), 256, ATTN_SMEM_BYTES>>>(gq, gk, gv, ga);

    gemm512_kernel<0><<<gg, 256>>>(ga, Wo, bo, out);
}

// round 2
// speedup vs baseline: 1.0741x; 1.0741x over previous
#include <cuda_runtime.h>

#define HIDDEN 512
#define HEADS  8
#define HD     64
#define BATCH  2
#define SEQ    4096
#define BH     (BATCH * HEADS)      // 16
#define MTOT   (BATCH * SEQ)        // 8192
#define LOG2E  1.44269504f

// Scratch (allocation-free rule: __device__ globals)
__device__ float g_q[(size_t)BH * SEQ * HD];
__device__ float g_k[(size_t)BH * SEQ * HD];
__device__ float g_v[(size_t)BH * SEQ * HD];
__device__ float g_attn[(size_t)MTOT * HIDDEN];

// ---------------------------------------------------------------------------
// Tiled fp32 GEMM: out[8192,512] = X[8192,512] @ W[512,512] + bias
// BM=128, BN=128, BK=16; 256 threads as 16x16, each computes 8x8
// (two 8x4 column groups 64 apart for conflict-free b-loads).
// HEADSPLIT=1: write into [B*H, S, 64] layout (each col group = one head)
// ---------------------------------------------------------------------------
template <int HEADSPLIT>
__global__ __launch_bounds__(256, 2) void gemm512_kernel(
    const float* __restrict__ X, const float* __restrict__ W,
    const float* __restrict__ bias, float* __restrict__ out)
{
    __shared__ float Xt[16 * 132];   // transposed X tile [k][m], stride 132
    __shared__ float Ws[16 * 128];   // W tile [k][n]

    const int tx = threadIdx.x & 15;
    const int ty = threadIdx.x >> 4;
    const int n0 = blockIdx.x * 128;
    const int m0 = blockIdx.y * 128;

    float acc[8][8];
#pragma unroll
    for (int i = 0; i < 8; ++i)
#pragma unroll
        for (int j = 0; j < 8; ++j) acc[i][j] = 0.f;

    for (int kt = 0; kt < HIDDEN; kt += 16) {
        __syncthreads();
        // X tile [128 x 16] -> Xt transposed (2-way STS conflict, negligible)
        for (int i = threadIdx.x; i < 512; i += 256) {
            int m  = i >> 2;
            int k4 = (i & 3) * 4;
            float4 v = *(const float4*)(X + (size_t)(m0 + m) * HIDDEN + kt + k4);
            Xt[(k4 + 0) * 132 + m] = v.x;
            Xt[(k4 + 1) * 132 + m] = v.y;
            Xt[(k4 + 2) * 132 + m] = v.z;
            Xt[(k4 + 3) * 132 + m] = v.w;
        }
        // W tile [16 x 128]
        for (int i = threadIdx.x; i < 512; i += 256) {
            int k  = i >> 5;
            int n4 = (i & 31) * 4;
            *(float4*)(Ws + k * 128 + n4) =
                *(const float4*)(W + (size_t)(kt + k) * HIDDEN + n0 + n4);
        }
        __syncthreads();

#pragma unroll
        for (int kk = 0; kk < 16; ++kk) {
            float4 a0 = *(const float4*)(Xt + kk * 132 + ty * 8);
            float4 a1 = *(const float4*)(Xt + kk * 132 + ty * 8 + 4);
            float4 b0 = *(const float4*)(Ws + kk * 128 + tx * 4);
            float4 b1 = *(const float4*)(Ws + kk * 128 + 64 + tx * 4);
            float a[8] = {a0.x, a0.y, a0.z, a0.w, a1.x, a1.y, a1.z, a1.w};
#pragma unroll
            for (int i = 0; i < 8; ++i) {
                acc[i][0] += a[i] * b0.x;
                acc[i][1] += a[i] * b0.y;
                acc[i][2] += a[i] * b0.z;
                acc[i][3] += a[i] * b0.w;
                acc[i][4] += a[i] * b1.x;
                acc[i][5] += a[i] * b1.y;
                acc[i][6] += a[i] * b1.z;
                acc[i][7] += a[i] * b1.w;
            }
        }
    }

    float4 bvA = *(const float4*)(bias + n0 + tx * 4);
    float4 bvB = *(const float4*)(bias + n0 + 64 + tx * 4);
#pragma unroll
    for (int i = 0; i < 8; ++i) {
        int m = m0 + ty * 8 + i;
        float4 rA = make_float4(acc[i][0] + bvA.x, acc[i][1] + bvA.y,
                                acc[i][2] + bvA.z, acc[i][3] + bvA.w);
        float4 rB = make_float4(acc[i][4] + bvB.x, acc[i][5] + bvB.y,
                                acc[i][6] + bvB.z, acc[i][7] + bvB.w);
        if (HEADSPLIT) {
            int b_ = m >> 12;
            int s_ = m & (SEQ - 1);
            int hA = blockIdx.x * 2;
            float* baseA = out + ((size_t)(b_ * HEADS + hA) * SEQ + s_) * HD + tx * 4;
            float* baseB = out + ((size_t)(b_ * HEADS + hA + 1) * SEQ + s_) * HD + tx * 4;
            *(float4*)baseA = rA;
            *(float4*)baseB = rB;
        } else {
            *(float4*)(out + (size_t)m * HIDDEN + n0 + tx * 4) = rA;
            *(float4*)(out + (size_t)m * HIDDEN + n0 + 64 + tx * 4) = rB;
        }
    }
}

// ---------------------------------------------------------------------------
// Flash attention, fp32. CTA: 128 q-rows of one (b,h); 64-key tiles.
// 256 threads as 16x16; S-tile 8x4 per thread; softmax in base-2.
// smem: Qt[64][132] (transposed, pre-scaled by 0.125*log2e),
//       Kt[64][64] ([k][key]), Vs[64][64], Ps[128][68]
// ---------------------------------------------------------------------------
#define ATTN_SMEM_FLOATS (64 * 132 + 64 * 64 + 64 * 64 + 128 * 68)
#define ATTN_SMEM_BYTES  (ATTN_SMEM_FLOATS * 4)

__global__ __launch_bounds__(256, 2) void attn_kernel(
    const float* __restrict__ Qg, const float* __restrict__ Kg,
    const float* __restrict__ Vg, float* __restrict__ Og)
{
    extern __shared__ float sm[];
    float* Qt = sm;                  // 64 x 132  [k][qrow]
    float* Kt = sm + 64 * 132;       // 64 x 64   [k][key]
    float* Vs = Kt + 64 * 64;        // 64 x 64   [key][hd]
    float* Ps = Vs + 64 * 64;        // 128 x 68  [qrow][key]

    const int tid = threadIdx.x;
    const int tx  = tid & 15;
    const int ty  = tid >> 4;
    const int bh  = blockIdx.y;
    const int q0  = blockIdx.x * 128;

    const float* Qp = Qg + ((size_t)bh * SEQ + q0) * HD;
    const float* Kp = Kg + (size_t)bh * SEQ * HD;
    const float* Vp = Vg + (size_t)bh * SEQ * HD;

    // Load + transpose Q (fold softmax scale and log2e): Qt[k][m]
    {
        const float sc = 0.125f * LOG2E;
        for (int i = tid; i < 2048; i += 256) {
            int m  = i >> 4;
            int k4 = (i & 15) * 4;
            float4 v = *(const float4*)(Qp + m * HD + k4);
            Qt[(k4 + 0) * 132 + m] = v.x * sc;
            Qt[(k4 + 1) * 132 + m] = v.y * sc;
            Qt[(k4 + 2) * 132 + m] = v.z * sc;
            Qt[(k4 + 3) * 132 + m] = v.w * sc;
        }
    }

    float O_[8][4];
    float m_[8], l_[8];
#pragma unroll
    for (int i = 0; i < 8; ++i) {
        m_[i] = -1e30f; l_[i] = 0.f;
#pragma unroll
        for (int j = 0; j < 4; ++j) O_[i][j] = 0.f;
    }

    for (int t = 0; t < SEQ / 64; ++t) {
        __syncthreads();   // prev iter done with Kt/Vs (Qt ready on t==0)
        const float* Kpt = Kp + (size_t)t * 64 * HD;
        const float* Vpt = Vp + (size_t)t * 64 * HD;
        // V tile: contiguous
        for (int i = tid; i < 1024; i += 256)
            ((float4*)Vs)[i] = ((const float4*)Vpt)[i];
        // K tile: transpose (scattered LDG, conflict-free STS)
        for (int i = tid; i < 1024; i += 256) {
            int n  = i & 63;
            int k4 = (i >> 6) * 4;
            float4 v = *(const float4*)(Kpt + n * HD + k4);
            Kt[(k4 + 0) * 64 + n] = v.x;
            Kt[(k4 + 1) * 64 + n] = v.y;
            Kt[(k4 + 2) * 64 + n] = v.z;
            Kt[(k4 + 3) * 64 + n] = v.w;
        }
        __syncthreads();

        // S = Q @ K^T for this 128x64 tile (log2-domain scores)
        float s_[8][4];
#pragma unroll
        for (int i = 0; i < 8; ++i)
#pragma unroll
            for (int j = 0; j < 4; ++j) s_[i][j] = 0.f;

#pragma unroll 16
        for (int kk = 0; kk < 64; ++kk) {
            float4 a0 = *(const float4*)(Qt + kk * 132 + ty * 8);
            float4 a1 = *(const float4*)(Qt + kk * 132 + ty * 8 + 4);
            float4 b  = *(const float4*)(Kt + kk * 64 + tx * 4);
            float a[8] = {a0.x, a0.y, a0.z, a0.w, a1.x, a1.y, a1.z, a1.w};
#pragma unroll
            for (int i = 0; i < 8; ++i) {
                s_[i][0] += a[i] * b.x;
                s_[i][1] += a[i] * b.y;
                s_[i][2] += a[i] * b.z;
                s_[i][3] += a[i] * b.w;
            }
        }

        // Online softmax (base-2); row stats across 16-lane tx group
#pragma unroll
        for (int i = 0; i < 8; ++i) {
            float mx = fmaxf(fmaxf(s_[i][0], s_[i][1]), fmaxf(s_[i][2], s_[i][3]));
#pragma unroll
            for (int off = 8; off; off >>= 1)
                mx = fmaxf(mx, __shfl_xor_sync(0xffffffffu, mx, off));
            float mnew = fmaxf(m_[i], mx);
            float corr = exp2f(m_[i] - mnew);
            m_[i] = mnew;
            float p0 = exp2f(s_[i][0] - mnew);
            float p1 = exp2f(s_[i][1] - mnew);
            float p2 = exp2f(s_[i][2] - mnew);
            float p3 = exp2f(s_[i][3] - mnew);
            float rs = (p0 + p1) + (p2 + p3);
#pragma unroll
            for (int off = 8; off; off >>= 1)
                rs += __shfl_xor_sync(0xffffffffu, rs, off);
            l_[i] = l_[i] * corr + rs;
#pragma unroll
            for (int j = 0; j < 4; ++j) O_[i][j] *= corr;
            *(float4*)(Ps + (ty * 8 + i) * 68 + tx * 4) = make_float4(p0, p1, p2, p3);
        }
        __syncthreads();   // Ps visible; Kt/Vs still needed for PV below (Vs)

        // O += P @ V
#pragma unroll 8
        for (int kk = 0; kk < 64; ++kk) {
            float4 b = *(const float4*)(Vs + kk * 64 + tx * 4);
            float a[8];
#pragma unroll
            for (int i = 0; i < 8; ++i) a[i] = Ps[(ty * 8 + i) * 68 + kk];
#pragma unroll
            for (int i = 0; i < 8; ++i) {
                O_[i][0] += a[i] * b.x;
                O_[i][1] += a[i] * b.y;
                O_[i][2] += a[i] * b.z;
                O_[i][3] += a[i] * b.w;
            }
        }
    }

    // Epilogue: O /= l; write to g_attn flat [B*S, 512]
    const int b_ = bh >> 3;
    const int h  = bh & 7;
#pragma unroll
    for (int i = 0; i < 8; ++i) {
        float inv = 1.0f / l_[i];
        float4 r = make_float4(O_[i][0] * inv, O_[i][1] * inv,
                               O_[i][2] * inv, O_[i][3] * inv);
        size_t row = (size_t)b_ * SEQ + q0 + ty * 8 + i;
        *(float4*)(Og + row * HIDDEN + h * HD + tx * 4) = r;
    }
}

// ---------------------------------------------------------------------------
extern "C" void kernel_launch(void* const* d_in, const int* in_sizes, int n_in,
                              void* d_out, int out_size)
{
    const float* x  = (const float*)d_in[0];
    const float* Wq = (const float*)d_in[1];
    const float* bq = (const float*)d_in[2];
    const float* Wk = (const float*)d_in[3];
    const float* bk = (const float*)d_in[4];
    const float* Wv = (const float*)d_in[5];
    const float* bv = (const float*)d_in[6];
    const float* Wo = (const float*)d_in[7];
    const float* bo = (const float*)d_in[8];
    float* out = (float*)d_out;

    float *gq, *gk, *gv, *ga;
    cudaGetSymbolAddress((void**)&gq, g_q);
    cudaGetSymbolAddress((void**)&gk, g_k);
    cudaGetSymbolAddress((void**)&gv, g_v);
    cudaGetSymbolAddress((void**)&ga, g_attn);

    cudaFuncSetAttribute(attn_kernel,
                         cudaFuncAttributeMaxDynamicSharedMemorySize,
                         ATTN_SMEM_BYTES);

    dim3 gg(HIDDEN / 128, MTOT / 128);   // (4, 64)
    gemm512_kernel<1><<<gg, 256>>>(x, Wq, bq, gq);
    gemm512_kernel<1><<<gg, 256>>>(x, Wk, bk, gk);
    gemm512_kernel<1><<<gg, 256>>>(x, Wv, bv, gv);

    attn_kernel<<<dim3(SEQ / 128, BH), 256, ATTN_SMEM_BYTES>>>(gq, gk, gv, ga);

    gemm512_kernel<0><<<gg, 256>>>(ga, Wo, bo, out);
}